// round 15
// baseline (speedup 1.0000x reference)
#include <cuda_runtime.h>
#include <cuda_fp16.h>
#include <cstdint>

#define CIN 3
#define NY  31
#define POS 961
#define POq 48

// ---- smem layout (bytes) ----
#define SBIAS 0          // 48 floats
#define B0    1024       // B tile: 64 k-rows x 128B (48 halves used), swizzled, fp16
#define B1    9216
#define SMEM_BYTES 17408

__device__ __forceinline__ uint32_t smem_u32(const void* p) {
    uint32_t a;
    asm("{ .reg .u64 t; cvta.to.shared.u64 t, %1; cvt.u32.u64 %0, t; }" : "=r"(a) : "l"(p));
    return a;
}
__device__ __forceinline__ void ldsm_x4t(uint32_t& r0, uint32_t& r1, uint32_t& r2, uint32_t& r3,
                                         uint32_t a) {
    asm volatile("ldmatrix.sync.aligned.m8n8.x4.trans.shared.b16 {%0,%1,%2,%3}, [%4];"
                 : "=r"(r0), "=r"(r1), "=r"(r2), "=r"(r3) : "r"(a));
}
__device__ __forceinline__ void mma16816(float& d0, float& d1, float& d2, float& d3,
                                         uint32_t a0, uint32_t a1, uint32_t a2, uint32_t a3,
                                         uint32_t b0, uint32_t b1) {
    asm volatile("mma.sync.aligned.m16n8k16.row.col.f32.f16.f16.f32 "
                 "{%0,%1,%2,%3}, {%4,%5,%6,%7}, {%8,%9}, {%0,%1,%2,%3};"
                 : "+f"(d0), "+f"(d1), "+f"(d2), "+f"(d3)
                 : "r"(a0), "r"(a1), "r"(a2), "r"(a3), "r"(b0), "r"(b1));
}
__device__ __forceinline__ uint32_t pack_hi(float v0, float v1) {
    __half h0 = __float2half_rn(v0), h1 = __float2half_rn(v1);
    return (uint32_t)__half_as_ushort(h0) | ((uint32_t)__half_as_ushort(h1) << 16);
}
__device__ __forceinline__ void sts32(uint32_t a, uint32_t v) {
    asm volatile("st.shared.b32 [%0], %1;" :: "r"(a), "r"(v) : "memory");
}

extern __shared__ char smem[];

__global__ void __launch_bounds__(128, 4)
ttn_conv_hmma_kernel(const float* __restrict__ x,
                     const float* __restrict__ w,
                     const float* __restrict__ bias,
                     float* __restrict__ out)
{
    const int pos  = blockIdx.x;           // one CTA per position, M=128
    const int xx   = pos / NY;
    const int yy   = pos - xx * NY;
    const int tid  = threadIdx.x;
    const int lane = tid & 31;
    const int wid  = tid >> 5;
    const uint32_t sb = smem_u32(smem);
    float* sbias = (float*)(smem + SBIAS);

    if (tid < POq) {
        int p = tid / 6, o = tid - p * 6;
        sbias[tid] = bias[((p * 31 + xx) * 31 + yy) * 6 + o];
    }

    const int bp  = tid >> 4;     // p block (0..7) for weight loads
    const int t16 = tid & 15;

    float D[48];                  // [mt][nt][r] = 2*6*4
    #pragma unroll
    for (int i = 0; i < 48; i++) D[i] = 0.f;

    // ---- A register-resident: warp owns rows wid*32 .. wid*32+31 (2 m-tiles) ----
    // per mt: rows rA = wid*32 + mt*16 + (lane>>2), rB = rA + 8
    const int rbase = wid * 32 + (lane >> 2);
    const int cq = (lane & 3) >> 1;    // cv indices cq, cq+2
    const int dr = (lane & 1) * 2;     // dv indices dr, dr+1
    float avA[2][4], bvA[2][4], cdA[2][4];
    float avB[2][4], bvB[2][4], cdB[2][4];

    auto load_x = [&](int c) {
        #pragma unroll
        for (int mt = 0; mt < 2; mt++) {
            const int rA = rbase + mt * 16;
            const float* xpA = x + ((size_t)rA * CIN + c) * 4096 + xx * 32 + yy;
            const float* xpB = xpA + (size_t)8 * CIN * 4096;
            #pragma unroll
            for (int i = 0; i < 4; i++) {
                avA[mt][i] = xpA[i * 1024];          avB[mt][i] = xpB[i * 1024];
                bvA[mt][i] = xpA[i * 1024 + 32];     bvB[mt][i] = xpB[i * 1024 + 32];
            }
            float c0a = xpA[cq * 1024 + 1],  c1a = xpA[(cq + 2) * 1024 + 1];
            float d0a = xpA[dr * 1024 + 33], d1a = xpA[(dr + 1) * 1024 + 33];
            cdA[mt][0] = c0a * d0a; cdA[mt][1] = c0a * d1a;
            cdA[mt][2] = c1a * d0a; cdA[mt][3] = c1a * d1a;
            float c0b = xpB[cq * 1024 + 1],  c1b = xpB[(cq + 2) * 1024 + 1];
            float d0b = xpB[dr * 1024 + 33], d1b = xpB[(dr + 1) * 1024 + 33];
            cdB[mt][0] = c0b * d0b; cdB[mt][1] = c0b * d1b;
            cdB[mt][2] = c1b * d0b; cdB[mt][3] = c1b * d1b;
        }
    };

    float4 fb[3];                 // weight batch buffer (half a stage)
    auto ldgB = [&](int st, int batch) {  // stage st (0..11): p-block slice, rows 3*batch..
        int c = st >> 2;
        const float* gw = w + ((size_t)(c * 8 + bp) * POS + pos) * 1536 + (st & 3) * 384;
        #pragma unroll
        for (int r = 0; r < 3; r++) fb[r] = ((const float4*)gw)[t16 + 16 * (r + 3 * batch)];
    };
    auto stsB = [&](int par, int batch) { // write fb into B buffer `par`
        const uint32_t bh = sb + (par ? B1 : B0);
        #pragma unroll
        for (int r = 0; r < 3; r++) {
            const float* fp = &fb[r].x;
            const int rr = r + 3 * batch;
            #pragma unroll
            for (int up = 0; up < 2; up++) {
                int e0 = t16 * 4 + up * 2 + rr * 64;  // even; e0%6 in {0,2,4} -> same-k pair
                int k  = e0 / 6, o = e0 - 6 * k;      // k 0..63
                uint32_t n   = (uint32_t)(bp * 6 + o);
                uint32_t off = (uint32_t)k * 128u + 16u * ((n >> 3) ^ ((uint32_t)k & 7u))
                             + (n & 7u) * 2u;
                sts32(bh + off, pack_hi(fp[up * 2], fp[up * 2 + 1]));
            }
        }
    };

    // ---- prologue: stage 0 into buffer 0 ----
    load_x(0);
    ldgB(0, 0); stsB(0, 0);
    ldgB(0, 1); stsB(0, 1);
    __syncthreads();

    // ---- pipeline: c (dynamic) x sl (static) = 12 stages of K=64 ----
    #pragma unroll 1
    for (int c = 0; c < CIN; c++) {
        if (c) load_x(c);
        #pragma unroll
        for (int sl = 0; sl < 4; sl++) {
            const int st  = c * 4 + sl;
            const int buf = st & 1;
            const uint32_t bh = sb + (buf ? B1 : B0);

            if (st < 11) ldgB(st + 1, 0);

            // ---- compute halves interleaved with next-stage staging ----
            #pragma unroll
            for (int half = 0; half < 2; half++) {
                #pragma unroll
                for (int sh = 0; sh < 2; sh++) {
                    const int s16 = half * 2 + sh;
                    uint32_t Bh[12];
                    uint32_t krow = (uint32_t)(s16 * 16 + ((lane >> 3) & 1) * 8 + (lane & 7));
                    #pragma unroll
                    for (int ntp = 0; ntp < 3; ntp++) {
                        uint32_t n    = (uint32_t)((ntp * 2 + (lane >> 4)) * 8);
                        uint32_t boff = krow * 128u + 16u * ((n >> 3) ^ (krow & 7u));
                        ldsm_x4t(Bh[ntp * 4], Bh[ntp * 4 + 1],
                                 Bh[ntp * 4 + 2], Bh[ntp * 4 + 3], bh + boff);
                    }
                    #pragma unroll
                    for (int mt = 0; mt < 2; mt++) {
                        const float ab1 = avA[mt][sl] * bvA[mt][s16];
                        const float ab2 = avB[mt][sl] * bvB[mt][s16];
                        uint32_t Ah0 = pack_hi(ab1 * cdA[mt][0], ab1 * cdA[mt][1]);
                        uint32_t Ah1 = pack_hi(ab2 * cdB[mt][0], ab2 * cdB[mt][1]);
                        uint32_t Ah2 = pack_hi(ab1 * cdA[mt][2], ab1 * cdA[mt][3]);
                        uint32_t Ah3 = pack_hi(ab2 * cdB[mt][2], ab2 * cdB[mt][3]);
                        #pragma unroll
                        for (int nt = 0; nt < 6; nt++) {
                            float* d = D + (mt * 6 + nt) * 4;
                            uint32_t b0 = (nt & 1) ? Bh[(nt >> 1) * 4 + 2] : Bh[(nt >> 1) * 4 + 0];
                            uint32_t b1 = (nt & 1) ? Bh[(nt >> 1) * 4 + 3] : Bh[(nt >> 1) * 4 + 1];
                            mma16816(d[0], d[1], d[2], d[3], Ah0, Ah1, Ah2, Ah3, b0, b1);
                        }
                    }
                }
                if (st < 11) {
                    stsB(buf ^ 1, half);            // write next-stage batch to other buffer
                    if (half == 0) ldgB(st + 1, 1); // fetch second batch
                }
            }
            __syncthreads();
        }
    }

    // ---- epilogue ----
    #pragma unroll
    for (int mt = 0; mt < 2; mt++)
        #pragma unroll
        for (int nt = 0; nt < 6; nt++)
            #pragma unroll
            for (int r = 0; r < 4; r++) {
                int grow = wid * 32 + mt * 16 + (lane >> 2) + ((r >= 2) ? 8 : 0);
                int q    = nt * 8 + (lane & 3) * 2 + (r & 1);
                out[((size_t)grow * POq + q) * POS + pos] = D[(mt * 6 + nt) * 4 + r] + sbias[q];
            }
}

extern "C" void kernel_launch(void* const* d_in, const int* in_sizes, int n_in,
                              void* d_out, int out_size) {
    const float* x    = (const float*)d_in[0];
    const float* w    = (const float*)d_in[1];
    const float* bias = (const float*)d_in[2];
    float* out        = (float*)d_out;
    (void)in_sizes; (void)n_in; (void)out_size;

    cudaFuncSetAttribute(ttn_conv_hmma_kernel,
                         cudaFuncAttributeMaxDynamicSharedMemorySize, SMEM_BYTES);
    ttn_conv_hmma_kernel<<<POS, 128, SMEM_BYTES>>>(x, w, bias, out);
}